// round 9
// baseline (speedup 1.0000x reference)
#include <cuda_runtime.h>
#include <utility>
#include <math.h>

// ============================================================================
// Compile-time real-basis Wigner 3j (Clebsch-Gordan) coefficients.
// Mirrors the numpy reference exactly, evaluated by the C++ front end so that
// every nonzero entry becomes an FFMA immediate and every zero vanishes.
// All helpers are __host__ __device__ so device code may constant-evaluate
// them without --expt-relaxed-constexpr.
// ============================================================================
namespace cgc {

__host__ __device__ constexpr double cfact(int n) {
  double r = 1.0;
  for (int i = 2; i <= n; ++i) r *= (double)i;
  return r;
}
__host__ __device__ constexpr double psign(int k) {
  return (k % 2 == 0) ? 1.0 : -1.0;
}
__host__ __device__ constexpr double csqrt(double x) {
  if (x <= 0.0) return 0.0;
  double r = x >= 1.0 ? x : 1.0;
  for (int i = 0; i < 200; ++i) {
    double nr = 0.5 * (r + x / r);
    if (nr == r) break;
    r = nr;
  }
  return r;
}

// complex-basis Wigner 3j value for (l1,l2,l3; m1,m2,-m1-m2)
__host__ __device__ constexpr double w3jc(int l1, int l2, int l3, int m1,
                                          int m2) {
  const int m3 = -m1 - m2;
  if (m3 < -l3 || m3 > l3) return 0.0;
  const double tri = cfact(l1 + l2 - l3) * cfact(l1 - l2 + l3) *
                     cfact(-l1 + l2 + l3) / cfact(l1 + l2 + l3 + 1);
  const double pref =
      psign(l1 - l2 - m3) *
      csqrt(tri * cfact(l1 + m1) * cfact(l1 - m1) * cfact(l2 + m2) *
            cfact(l2 - m2) * cfact(l3 + m3) * cfact(l3 - m3));
  int t0 = 0;
  if (l2 - l3 - m1 > t0) t0 = l2 - l3 - m1;
  if (l1 - l3 + m2 > t0) t0 = l1 - l3 + m2;
  int t1 = l1 + l2 - l3;
  if (l1 - m1 < t1) t1 = l1 - m1;
  if (l2 + m2 < t1) t1 = l2 + m2;
  double s = 0.0;
  for (int t = t0; t <= t1; ++t) {
    s += psign(t) / (cfact(t) * cfact(l1 + l2 - l3 - t) * cfact(l1 - m1 - t) *
                     cfact(l2 + m2 - t) * cfact(l3 - l2 + m1 + t) *
                     cfact(l3 - l1 - m2 + t));
  }
  return pref * s;
}

// one row of the complex->real change-of-basis matrix U(l): at most 2 nonzeros
struct URow {
  int n;
  int col[2];
  double re[2];
  double im[2];
};

__host__ __device__ constexpr URow urow(int l, int i) {
  URow r{};
  const double s2 = csqrt(0.5);
  const int mu = i - l;
  if (mu == 0) {
    r.n = 1;
    r.col[0] = l; r.re[0] = 1.0; r.im[0] = 0.0;
  } else if (mu > 0) {
    r.n = 2;
    r.col[0] = l + mu; r.re[0] = psign(mu) * s2; r.im[0] = 0.0;
    r.col[1] = l - mu; r.re[1] = s2;             r.im[1] = 0.0;
  } else {
    const int m = -mu;
    r.n = 2;
    r.col[0] = l - m; r.re[0] = 0.0; r.im[0] = s2;
    r.col[1] = l + m; r.re[1] = 0.0; r.im[1] = -psign(m) * s2;
  }
  return r;
}

// real-basis 3j entry: Re( sum_{a,b,c} U1[i,a] U2[j,b] U3[k,c] C[a,b,c] )
__host__ __device__ constexpr double cg_real(int l1, int l2, int l3, int i,
                                             int j, int k) {
  const URow r1 = urow(l1, i);
  const URow r2 = urow(l2, j);
  const URow r3 = urow(l3, k);
  double acc = 0.0;
  for (int a = 0; a < r1.n; ++a)
    for (int b = 0; b < r2.n; ++b) {
      const int m1 = r1.col[a] - l1;
      const int m2 = r2.col[b] - l2;
      const int m3 = -m1 - m2;
      if (m3 < -l3 || m3 > l3) continue;
      const int cidx = m3 + l3;
      for (int c = 0; c < r3.n; ++c) {
        if (r3.col[c] != cidx) continue;
        const double re12 = r1.re[a] * r2.re[b] - r1.im[a] * r2.im[b];
        const double im12 = r1.re[a] * r2.im[b] + r1.im[a] * r2.re[b];
        const double rp = re12 * r3.re[c] - im12 * r3.im[c];
        if (rp != 0.0) acc += rp * w3jc(l1, l2, l3, m1, m2);
      }
    }
  return acc;
}

}  // namespace cgc

// ============================================================================
// Fully-unrolled tensor-product generators. Each nonzero CG entry becomes one
// FFMA with an immediate constant; zeros are eliminated at compile time.
// ============================================================================
template <int L1, int L2, int LO, int K, int I, int J>
__device__ __forceinline__ void add_term(float& a0, float& a1,
                                         const float* __restrict__ x,
                                         const float* __restrict__ y) {
  constexpr float c = (float)cgc::cg_real(L1, L2, LO, I, J, K);
  if constexpr (c > 1e-7f || c < -1e-7f) {
    if constexpr (((I + J) & 1) == 0)
      a0 += c * (x[I] * y[J]);
    else
      a1 += c * (x[I] * y[J]);
  }
}

template <int L1, int L2, int LO, int K, int I, int... Js>
__device__ __forceinline__ void add_row(float& a0, float& a1, const float* x,
                                        const float* y,
                                        std::integer_sequence<int, Js...>) {
  (add_term<L1, L2, LO, K, I, Js>(a0, a1, x, y), ...);
}

template <int L1, int L2, int LO, int K, int... Is>
__device__ __forceinline__ void add_all(float& a0, float& a1, const float* x,
                                        const float* y,
                                        std::integer_sequence<int, Is...>) {
  (add_row<L1, L2, LO, K, Is>(a0, a1, x, y,
                              std::make_integer_sequence<int, 2 * L2 + 1>{}),
   ...);
}

template <int L1, int L2, int LO, int K>
__device__ __forceinline__ float tp_k(const float* x, const float* y) {
  float a0 = 0.f, a1 = 0.f;
  add_all<L1, L2, LO, K>(a0, a1, x, y,
                         std::make_integer_sequence<int, 2 * L1 + 1>{});
  return a0 + a1;
}

template <int L1, int L2, int LO, int... Ks>
__device__ __forceinline__ void tp_all_impl(float* __restrict__ t,
                                            const float* x, const float* y,
                                            std::integer_sequence<int, Ks...>) {
  ((t[Ks] = tp_k<L1, L2, LO, Ks>(x, y)), ...);
}
template <int L1, int L2, int LO>
__device__ __forceinline__ void tp_all(float* t, const float* x,
                                       const float* y) {
  tp_all_impl<L1, L2, LO>(t, x, y,
                          std::make_integer_sequence<int, 2 * LO + 1>{});
}

// ============================================================================
// Main kernel: one thread = one pixel. Block stages a 3-row x (TILE+2)-pixel
// x 22-channel halo tile in shared memory (padded to 23 floats -> LDS lane
// stride 23 is odd => conflict-free). Outputs written as float4 (16B-aligned:
// 36 floats = 144B, 52 floats = 208B per pixel).
// ============================================================================
constexpr int TILE = 128;
constexpr int HALO = TILE + 2;

__global__ __launch_bounds__(TILE) void esc_kernel(
    const float* __restrict__ f4, const float* __restrict__ f6,
    const float* __restrict__ sw, const float* __restrict__ tw,
    float* __restrict__ out, int H, int W) {
  __shared__ float sh[3][HALO][23];
  const int tid = threadIdx.x;
  const int h = blockIdx.y;
  const int w0 = blockIdx.x * TILE;

  // ---- cooperative halo load (coalesced: consecutive e -> consecutive ch,px)
  for (int e = tid; e < 3 * HALO * 22; e += TILE) {
    int r = e / (HALO * 22);
    int rem = e - r * (HALO * 22);
    int tp = rem / 22;
    int ch = rem - tp * 22;
    int gh = h - 1 + r;
    gh = gh < 0 ? 0 : (gh >= H ? H - 1 : gh);
    int gw = w0 - 1 + tp;
    gw = gw < 0 ? 0 : (gw >= W ? W - 1 : gw);
    long nn = (long)gh * W + gw;
    sh[r][tp][ch] =
        (ch < 9) ? __ldg(f4 + nn * 9 + ch) : __ldg(f6 + nn * 13 + (ch - 9));
  }
  __syncthreads();

  const int w = w0 + tid;
  if (w >= W) return;
  const long n = (long)h * W + w;

  // ---- spatial weights (uniform across warp)
  float s9[9];
#pragma unroll
  for (int i = 0; i < 9; ++i) s9[i] = __ldg(sw + i);

  // ---- center x[22] and 3x3-aggregated y[22]
  float x[22], y[22];
#pragma unroll
  for (int ch = 0; ch < 22; ++ch) {
    float a = 0.f;
#pragma unroll
    for (int dr = 0; dr < 3; ++dr)
#pragma unroll
      for (int dc = 0; dc < 3; ++dc) a += s9[dr * 3 + dc] * sh[dr][tid + dc][ch];
    y[ch] = a;
    x[ch] = sh[1][tid + 1][ch];
  }

  // ---- per-copy path weights (4 copies x 8)
  float twr[32];
#pragma unroll
  for (int i = 0; i < 32; ++i) twr[i] = __ldg(tw + i);

  // ---- tensor products: t[path][k], shared across copies
  float t4[4][9];
  tp_all<4, 4, 4>(t4[0], x, y);
  tp_all<4, 6, 4>(t4[1], x, y + 9);
  tp_all<6, 4, 4>(t4[2], x + 9, y);
  tp_all<6, 6, 4>(t4[3], x + 9, y + 9);
  float t6[4][13];
  tp_all<4, 4, 6>(t6[0], x, y);
  tp_all<4, 6, 6>(t6[1], x, y + 9);
  tp_all<6, 4, 6>(t6[2], x + 9, y);
  tp_all<6, 6, 6>(t6[3], x + 9, y + 9);

  const float A4 = 1.5f;                 // sqrt(9/4)
  const float A6 = 1.8027756377319946f;  // sqrt(13/4)

  // Full 88-col layout: col = c*22 + d; d<9 -> out4[c][d], else out6[c][d-9].
  // f4_out = cols [0,36) + f4[col % 9]; f6_out = cols [36,88) + f6[(col-36)%13].

  // ---- region 1: f4_out, 36 floats, 9 x STG.128
  float* o1 = out + n * 36;
#pragma unroll
  for (int g = 0; g < 9; ++g) {
    float v[4];
#pragma unroll
    for (int q = 0; q < 4; ++q) {
      const int t = g * 4 + q;  // col 0..35
      const int c = t / 22;
      const int d = t - c * 22;
      float s;
      if (d < 9) {
        s = A4 * (twr[c * 8 + 0] * t4[0][d] + twr[c * 8 + 1] * t4[1][d] +
                  twr[c * 8 + 2] * t4[2][d] + twr[c * 8 + 3] * t4[3][d]);
      } else {
        const int k = d - 9;
        s = A6 * (twr[c * 8 + 4] * t6[0][k] + twr[c * 8 + 5] * t6[1][k] +
                  twr[c * 8 + 6] * t6[2][k] + twr[c * 8 + 7] * t6[3][k]);
      }
      v[q] = s + x[t % 9];
    }
    reinterpret_cast<float4*>(o1)[g] = make_float4(v[0], v[1], v[2], v[3]);
  }

  // ---- region 2: f6_out, 52 floats, 13 x STG.128
  float* o2 = out + (long)H * W * 36 + n * 52;
#pragma unroll
  for (int g = 0; g < 13; ++g) {
    float v[4];
#pragma unroll
    for (int q = 0; q < 4; ++q) {
      const int t = g * 4 + q;  // 0..51
      const int col = 36 + t;   // 36..87
      const int c = col / 22;
      const int d = col - c * 22;
      float s;
      if (d < 9) {
        s = A4 * (twr[c * 8 + 0] * t4[0][d] + twr[c * 8 + 1] * t4[1][d] +
                  twr[c * 8 + 2] * t4[2][d] + twr[c * 8 + 3] * t4[3][d]);
      } else {
        const int k = d - 9;
        s = A6 * (twr[c * 8 + 4] * t6[0][k] + twr[c * 8 + 5] * t6[1][k] +
                  twr[c * 8 + 6] * t6[2][k] + twr[c * 8 + 7] * t6[3][k]);
      }
      v[q] = s + x[9 + (t % 13)];
    }
    reinterpret_cast<float4*>(o2)[g] = make_float4(v[0], v[1], v[2], v[3]);
  }
}

// ============================================================================
extern "C" void kernel_launch(void* const* d_in, const int* in_sizes, int n_in,
                              void* d_out, int out_size) {
  const float* f4 = (const float*)d_in[0];
  const float* f6 = (const float*)d_in[1];
  const float* sw = (const float*)d_in[2];
  const float* tw = (const float*)d_in[3];
  float* out = (float*)d_out;

  const long n = (long)in_sizes[0] / 9;  // HW
  int W = (int)(sqrt((double)n) + 0.5);  // H = W = 768 in this problem
  if (W < 1) W = 1;
  int H = (int)(n / W);

  dim3 grid((W + TILE - 1) / TILE, H);
  esc_kernel<<<grid, TILE>>>(f4, f6, sw, tw, out, H, W);
}

// round 10
// speedup vs baseline: 1.0023x; 1.0023x over previous
#include <cuda_runtime.h>
#include <utility>
#include <math.h>

// ============================================================================
// Compile-time real-basis Wigner 3j (Clebsch-Gordan) coefficients.
// Mirrors the numpy reference exactly, evaluated by the C++ front end so that
// every nonzero entry becomes an FFMA immediate and every zero vanishes.
// All helpers are __host__ __device__ so device code may constant-evaluate
// them without --expt-relaxed-constexpr.
// ============================================================================
namespace cgc {

__host__ __device__ constexpr double cfact(int n) {
  double r = 1.0;
  for (int i = 2; i <= n; ++i) r *= (double)i;
  return r;
}
__host__ __device__ constexpr double psign(int k) {
  return (k % 2 == 0) ? 1.0 : -1.0;
}
__host__ __device__ constexpr double csqrt(double x) {
  if (x <= 0.0) return 0.0;
  double r = x >= 1.0 ? x : 1.0;
  for (int i = 0; i < 200; ++i) {
    double nr = 0.5 * (r + x / r);
    if (nr == r) break;
    r = nr;
  }
  return r;
}

// complex-basis Wigner 3j value for (l1,l2,l3; m1,m2,-m1-m2)
__host__ __device__ constexpr double w3jc(int l1, int l2, int l3, int m1,
                                          int m2) {
  const int m3 = -m1 - m2;
  if (m3 < -l3 || m3 > l3) return 0.0;
  const double tri = cfact(l1 + l2 - l3) * cfact(l1 - l2 + l3) *
                     cfact(-l1 + l2 + l3) / cfact(l1 + l2 + l3 + 1);
  const double pref =
      psign(l1 - l2 - m3) *
      csqrt(tri * cfact(l1 + m1) * cfact(l1 - m1) * cfact(l2 + m2) *
            cfact(l2 - m2) * cfact(l3 + m3) * cfact(l3 - m3));
  int t0 = 0;
  if (l2 - l3 - m1 > t0) t0 = l2 - l3 - m1;
  if (l1 - l3 + m2 > t0) t0 = l1 - l3 + m2;
  int t1 = l1 + l2 - l3;
  if (l1 - m1 < t1) t1 = l1 - m1;
  if (l2 + m2 < t1) t1 = l2 + m2;
  double s = 0.0;
  for (int t = t0; t <= t1; ++t) {
    s += psign(t) / (cfact(t) * cfact(l1 + l2 - l3 - t) * cfact(l1 - m1 - t) *
                     cfact(l2 + m2 - t) * cfact(l3 - l2 + m1 + t) *
                     cfact(l3 - l1 - m2 + t));
  }
  return pref * s;
}

// one row of the complex->real change-of-basis matrix U(l): at most 2 nonzeros
struct URow {
  int n;
  int col[2];
  double re[2];
  double im[2];
};

__host__ __device__ constexpr URow urow(int l, int i) {
  URow r{};
  const double s2 = csqrt(0.5);
  const int mu = i - l;
  if (mu == 0) {
    r.n = 1;
    r.col[0] = l; r.re[0] = 1.0; r.im[0] = 0.0;
  } else if (mu > 0) {
    r.n = 2;
    r.col[0] = l + mu; r.re[0] = psign(mu) * s2; r.im[0] = 0.0;
    r.col[1] = l - mu; r.re[1] = s2;             r.im[1] = 0.0;
  } else {
    const int m = -mu;
    r.n = 2;
    r.col[0] = l - m; r.re[0] = 0.0; r.im[0] = s2;
    r.col[1] = l + m; r.re[1] = 0.0; r.im[1] = -psign(m) * s2;
  }
  return r;
}

// real-basis 3j entry: Re( sum_{a,b,c} U1[i,a] U2[j,b] U3[k,c] C[a,b,c] )
__host__ __device__ constexpr double cg_real(int l1, int l2, int l3, int i,
                                             int j, int k) {
  const URow r1 = urow(l1, i);
  const URow r2 = urow(l2, j);
  const URow r3 = urow(l3, k);
  double acc = 0.0;
  for (int a = 0; a < r1.n; ++a)
    for (int b = 0; b < r2.n; ++b) {
      const int m1 = r1.col[a] - l1;
      const int m2 = r2.col[b] - l2;
      const int m3 = -m1 - m2;
      if (m3 < -l3 || m3 > l3) continue;
      const int cidx = m3 + l3;
      for (int c = 0; c < r3.n; ++c) {
        if (r3.col[c] != cidx) continue;
        const double re12 = r1.re[a] * r2.re[b] - r1.im[a] * r2.im[b];
        const double im12 = r1.re[a] * r2.im[b] + r1.im[a] * r2.re[b];
        const double rp = re12 * r3.re[c] - im12 * r3.im[c];
        if (rp != 0.0) acc += rp * w3jc(l1, l2, l3, m1, m2);
      }
    }
  return acc;
}

}  // namespace cgc

// ============================================================================
// Fully-unrolled tensor-product generators. Each nonzero CG entry becomes one
// FFMA with an immediate constant; zeros are eliminated at compile time.
// ============================================================================
template <int L1, int L2, int LO, int K, int I, int J>
__device__ __forceinline__ void add_term(float& a0, float& a1,
                                         const float* __restrict__ x,
                                         const float* __restrict__ y) {
  constexpr float c = (float)cgc::cg_real(L1, L2, LO, I, J, K);
  if constexpr (c > 1e-7f || c < -1e-7f) {
    if constexpr (((I + J) & 1) == 0)
      a0 += c * (x[I] * y[J]);
    else
      a1 += c * (x[I] * y[J]);
  }
}

template <int L1, int L2, int LO, int K, int I, int... Js>
__device__ __forceinline__ void add_row(float& a0, float& a1, const float* x,
                                        const float* y,
                                        std::integer_sequence<int, Js...>) {
  (add_term<L1, L2, LO, K, I, Js>(a0, a1, x, y), ...);
}

template <int L1, int L2, int LO, int K, int... Is>
__device__ __forceinline__ void add_all(float& a0, float& a1, const float* x,
                                        const float* y,
                                        std::integer_sequence<int, Is...>) {
  (add_row<L1, L2, LO, K, Is>(a0, a1, x, y,
                              std::make_integer_sequence<int, 2 * L2 + 1>{}),
   ...);
}

template <int L1, int L2, int LO, int K>
__device__ __forceinline__ float tp_k(const float* x, const float* y) {
  float a0 = 0.f, a1 = 0.f;
  add_all<L1, L2, LO, K>(a0, a1, x, y,
                         std::make_integer_sequence<int, 2 * L1 + 1>{});
  return a0 + a1;
}

template <int L1, int L2, int LO, int... Ks>
__device__ __forceinline__ void tp_all_impl(float* __restrict__ t,
                                            const float* x, const float* y,
                                            std::integer_sequence<int, Ks...>) {
  ((t[Ks] = tp_k<L1, L2, LO, Ks>(x, y)), ...);
}
template <int L1, int L2, int LO>
__device__ __forceinline__ void tp_all(float* t, const float* x,
                                       const float* y) {
  tp_all_impl<L1, L2, LO>(t, x, y,
                          std::make_integer_sequence<int, 2 * LO + 1>{});
}

// ============================================================================
// Main kernel: one thread = one pixel. Block stages a 3-row x (TILE+2)-pixel
// x 22-channel halo tile in shared memory (padded to 23 floats -> LDS lane
// stride 23 is odd => conflict-free). Outputs written as float4 (16B-aligned:
// 36 floats = 144B, 52 floats = 208B per pixel).
// ============================================================================
constexpr int TILE = 128;
constexpr int HALO = TILE + 2;

__global__ __launch_bounds__(TILE) void esc_kernel(
    const float* __restrict__ f4, const float* __restrict__ f6,
    const float* __restrict__ sw, const float* __restrict__ tw,
    float* __restrict__ out, int H, int W) {
  __shared__ float sh[3][HALO][23];
  const int tid = threadIdx.x;
  const int h = blockIdx.y;
  const int w0 = blockIdx.x * TILE;

  // ---- cooperative halo load (coalesced: consecutive e -> consecutive ch,px)
  for (int e = tid; e < 3 * HALO * 22; e += TILE) {
    int r = e / (HALO * 22);
    int rem = e - r * (HALO * 22);
    int tp = rem / 22;
    int ch = rem - tp * 22;
    int gh = h - 1 + r;
    gh = gh < 0 ? 0 : (gh >= H ? H - 1 : gh);
    int gw = w0 - 1 + tp;
    gw = gw < 0 ? 0 : (gw >= W ? W - 1 : gw);
    long nn = (long)gh * W + gw;
    sh[r][tp][ch] =
        (ch < 9) ? __ldg(f4 + nn * 9 + ch) : __ldg(f6 + nn * 13 + (ch - 9));
  }
  __syncthreads();

  const int w = w0 + tid;
  if (w >= W) return;
  const long n = (long)h * W + w;

  // ---- spatial weights (uniform across warp)
  float s9[9];
#pragma unroll
  for (int i = 0; i < 9; ++i) s9[i] = __ldg(sw + i);

  // ---- center x[22] and 3x3-aggregated y[22]
  float x[22], y[22];
#pragma unroll
  for (int ch = 0; ch < 22; ++ch) {
    float a = 0.f;
#pragma unroll
    for (int dr = 0; dr < 3; ++dr)
#pragma unroll
      for (int dc = 0; dc < 3; ++dc) a += s9[dr * 3 + dc] * sh[dr][tid + dc][ch];
    y[ch] = a;
    x[ch] = sh[1][tid + 1][ch];
  }

  // ---- per-copy path weights (4 copies x 8)
  float twr[32];
#pragma unroll
  for (int i = 0; i < 32; ++i) twr[i] = __ldg(tw + i);

  // ---- tensor products: t[path][k], shared across copies
  float t4[4][9];
  tp_all<4, 4, 4>(t4[0], x, y);
  tp_all<4, 6, 4>(t4[1], x, y + 9);
  tp_all<6, 4, 4>(t4[2], x + 9, y);
  tp_all<6, 6, 4>(t4[3], x + 9, y + 9);
  float t6[4][13];
  tp_all<4, 4, 6>(t6[0], x, y);
  tp_all<4, 6, 6>(t6[1], x, y + 9);
  tp_all<6, 4, 6>(t6[2], x + 9, y);
  tp_all<6, 6, 6>(t6[3], x + 9, y + 9);

  const float A4 = 1.5f;                 // sqrt(9/4)
  const float A6 = 1.8027756377319946f;  // sqrt(13/4)

  // Full 88-col layout: col = c*22 + d; d<9 -> out4[c][d], else out6[c][d-9].
  // f4_out = cols [0,36) + f4[col % 9]; f6_out = cols [36,88) + f6[(col-36)%13].

  // ---- region 1: f4_out, 36 floats, 9 x STG.128
  float* o1 = out + n * 36;
#pragma unroll
  for (int g = 0; g < 9; ++g) {
    float v[4];
#pragma unroll
    for (int q = 0; q < 4; ++q) {
      const int t = g * 4 + q;  // col 0..35
      const int c = t / 22;
      const int d = t - c * 22;
      float s;
      if (d < 9) {
        s = A4 * (twr[c * 8 + 0] * t4[0][d] + twr[c * 8 + 1] * t4[1][d] +
                  twr[c * 8 + 2] * t4[2][d] + twr[c * 8 + 3] * t4[3][d]);
      } else {
        const int k = d - 9;
        s = A6 * (twr[c * 8 + 4] * t6[0][k] + twr[c * 8 + 5] * t6[1][k] +
                  twr[c * 8 + 6] * t6[2][k] + twr[c * 8 + 7] * t6[3][k]);
      }
      v[q] = s + x[t % 9];
    }
    reinterpret_cast<float4*>(o1)[g] = make_float4(v[0], v[1], v[2], v[3]);
  }

  // ---- region 2: f6_out, 52 floats, 13 x STG.128
  float* o2 = out + (long)H * W * 36 + n * 52;
#pragma unroll
  for (int g = 0; g < 13; ++g) {
    float v[4];
#pragma unroll
    for (int q = 0; q < 4; ++q) {
      const int t = g * 4 + q;  // 0..51
      const int col = 36 + t;   // 36..87
      const int c = col / 22;
      const int d = col - c * 22;
      float s;
      if (d < 9) {
        s = A4 * (twr[c * 8 + 0] * t4[0][d] + twr[c * 8 + 1] * t4[1][d] +
                  twr[c * 8 + 2] * t4[2][d] + twr[c * 8 + 3] * t4[3][d]);
      } else {
        const int k = d - 9;
        s = A6 * (twr[c * 8 + 4] * t6[0][k] + twr[c * 8 + 5] * t6[1][k] +
                  twr[c * 8 + 6] * t6[2][k] + twr[c * 8 + 7] * t6[3][k]);
      }
      v[q] = s + x[9 + (t % 13)];
    }
    reinterpret_cast<float4*>(o2)[g] = make_float4(v[0], v[1], v[2], v[3]);
  }
}

// ============================================================================
extern "C" void kernel_launch(void* const* d_in, const int* in_sizes, int n_in,
                              void* d_out, int out_size) {
  const float* f4 = (const float*)d_in[0];
  const float* f6 = (const float*)d_in[1];
  const float* sw = (const float*)d_in[2];
  const float* tw = (const float*)d_in[3];
  float* out = (float*)d_out;

  const long n = (long)in_sizes[0] / 9;  // HW
  int W = (int)(sqrt((double)n) + 0.5);  // H = W = 768 in this problem
  if (W < 1) W = 1;
  int H = (int)(n / W);

  dim3 grid((W + TILE - 1) / TILE, H);
  esc_kernel<<<grid, TILE>>>(f4, f6, sw, tw, out, H, W);
}